// round 1
// baseline (speedup 1.0000x reference)
#include <cuda_runtime.h>
#include <math.h>

#define NEXP   8
#define TOKENS 2048
#define NEMBD  1024
#define DFF    4096

// Scratch for the intermediate activation h = gelu(x @ W1 + b1): [8, 2048, 4096] fp32.
// __device__ global (no runtime allocation — allocation guards).
__device__ float g_hidden[(size_t)NEXP * TOKENS * DFF];

__device__ __forceinline__ float gelu_exact(float x) {
    // jax.nn.gelu(approximate=False): 0.5 * x * (1 + erf(x / sqrt(2)))
    return 0.5f * x * (1.0f + erff(x * 0.70710678118654752440f));
}

// C[e] = act(A[e] @ B[e] + bias[e])   A:[M,K] row-major, B:[K,N] row-major, bias:[N]
// BM=BN=128, BK=16, TM=TN=8, 256 threads. All of M,N divisible by 128, K by 16.
template<int BM, int BN, int BK, int TM, int TN, bool DO_GELU>
__global__ __launch_bounds__(256, 2)
void gemm_bias_act(const float* __restrict__ A,
                   const float* __restrict__ B,
                   const float* __restrict__ Bias,
                   float* __restrict__ C,
                   int M, int N, int K)
{
    // nullptr => use the device scratch buffer (avoids host symbol-address plumbing)
    if (A == nullptr) A = g_hidden;
    float* Cout = (C == nullptr) ? g_hidden : C;

    const int e = blockIdx.z;
    A    += (size_t)e * M * K;
    B    += (size_t)e * K * N;
    Bias += (size_t)e * N;
    Cout += (size_t)e * M * N;

    __shared__ float As[BK][BM];   // K-major: As[k][m]
    __shared__ float Bs[BK][BN];   // Bs[k][n]

    const int tid = threadIdx.x;
    const int tx  = tid % (BN / TN);   // 0..15  (column group)
    const int ty  = tid / (BN / TN);   // 0..15  (row group)

    const int m0 = blockIdx.y * BM;
    const int n0 = blockIdx.x * BN;

    float acc[TM][TN];
    #pragma unroll
    for (int i = 0; i < TM; ++i)
        #pragma unroll
        for (int j = 0; j < TN; ++j)
            acc[i][j] = 0.0f;

    for (int kt = 0; kt < K; kt += BK) {
        // ---- load A tile: BM x BK (512 float4, 2 per thread), store transposed ----
        #pragma unroll
        for (int it = 0; it < (BM * BK) / (4 * 256); ++it) {
            int li  = tid + it * 256;
            int row = li >> 2;          // / (BK/4)
            int kq  = li & 3;           // % (BK/4)
            float4 av = *reinterpret_cast<const float4*>(&A[(size_t)(m0 + row) * K + kt + kq * 4]);
            As[kq * 4 + 0][row] = av.x;
            As[kq * 4 + 1][row] = av.y;
            As[kq * 4 + 2][row] = av.z;
            As[kq * 4 + 3][row] = av.w;
        }
        // ---- load B tile: BK x BN (512 float4, 2 per thread) ----
        #pragma unroll
        for (int it = 0; it < (BK * BN) / (4 * 256); ++it) {
            int li  = tid + it * 256;
            int row = li >> 5;          // / (BN/4)
            int nq  = li & 31;          // % (BN/4)
            float4 bv = *reinterpret_cast<const float4*>(&B[(size_t)(kt + row) * N + n0 + nq * 4]);
            *reinterpret_cast<float4*>(&Bs[row][nq * 4]) = bv;
        }
        __syncthreads();

        #pragma unroll
        for (int k = 0; k < BK; ++k) {
            float ra[TM], rb[TN];
            const float4* a4 = reinterpret_cast<const float4*>(&As[k][ty * TM]);
            float4 a0 = a4[0], a1 = a4[1];
            ra[0]=a0.x; ra[1]=a0.y; ra[2]=a0.z; ra[3]=a0.w;
            ra[4]=a1.x; ra[5]=a1.y; ra[6]=a1.z; ra[7]=a1.w;
            const float4* b4 = reinterpret_cast<const float4*>(&Bs[k][tx * TN]);
            float4 b0 = b4[0], b1 = b4[1];
            rb[0]=b0.x; rb[1]=b0.y; rb[2]=b0.z; rb[3]=b0.w;
            rb[4]=b1.x; rb[5]=b1.y; rb[6]=b1.z; rb[7]=b1.w;
            #pragma unroll
            for (int i = 0; i < TM; ++i)
                #pragma unroll
                for (int j = 0; j < TN; ++j)
                    acc[i][j] = fmaf(ra[i], rb[j], acc[i][j]);
        }
        __syncthreads();
    }

    // ---- epilogue: bias (+ exact GELU), vectorized stores ----
    float bb[TN];
    #pragma unroll
    for (int j = 0; j < TN; ++j)
        bb[j] = Bias[n0 + tx * TN + j];

    #pragma unroll
    for (int i = 0; i < TM; ++i) {
        float vals[TN];
        #pragma unroll
        for (int j = 0; j < TN; ++j) {
            float v = acc[i][j] + bb[j];
            vals[j] = DO_GELU ? gelu_exact(v) : v;
        }
        float* crow = &Cout[(size_t)(m0 + ty * TM + i) * N + n0 + tx * TN];
        *reinterpret_cast<float4*>(crow + 0) = make_float4(vals[0], vals[1], vals[2], vals[3]);
        *reinterpret_cast<float4*>(crow + 4) = make_float4(vals[4], vals[5], vals[6], vals[7]);
    }
}

extern "C" void kernel_launch(void* const* d_in, const int* in_sizes, int n_in,
                              void* d_out, int out_size)
{
    const float* x         = (const float*)d_in[0];  // [8, 2048, 1024]
    const float* c_fc      = (const float*)d_in[1];  // [8, 1024, 4096]
    const float* c_proj    = (const float*)d_in[2];  // [8, 4096, 1024]
    const float* fc_bias   = (const float*)d_in[3];  // [8, 1, 4096]
    const float* proj_bias = (const float*)d_in[4];  // [8, 1, 1024]
    float* out = (float*)d_out;                      // [8, 2048, 1024]

    dim3 block(256);

    // Kernel 1: h = gelu(x @ c_fc + fc_bias)   M=2048, N=4096, K=1024
    dim3 grid1(DFF / 128, TOKENS / 128, NEXP);
    gemm_bias_act<128, 128, 16, 8, 8, true><<<grid1, block>>>(
        x, c_fc, fc_bias, /*C=*/nullptr, TOKENS, DFF, NEMBD);

    // Kernel 2: out = h @ c_proj + proj_bias   M=2048, N=1024, K=4096
    dim3 grid2(NEMBD / 128, TOKENS / 128, NEXP);
    gemm_bias_act<128, 128, 16, 8, 8, false><<<grid2, block>>>(
        /*A=*/nullptr, c_proj, proj_bias, out, TOKENS, NEMBD, DFF);
}

// round 3
// speedup vs baseline: 2.1249x; 2.1249x over previous
#include <cuda_runtime.h>
#include <cuda_bf16.h>
#include <math.h>
#include <stdint.h>

#define NEXP   8
#define TOKENS 2048
#define NEMBD  1024
#define DFF    4096

// ---------------- device scratch (no runtime allocation) ----------------
__device__ __nv_bfloat16 g_xh[(size_t)NEXP * TOKENS * NEMBD];
__device__ __nv_bfloat16 g_xl[(size_t)NEXP * TOKENS * NEMBD];
__device__ __nv_bfloat16 g_w1h[(size_t)NEXP * DFF * NEMBD];   // [e][N=DFF][K=NEMBD]
__device__ __nv_bfloat16 g_w1l[(size_t)NEXP * DFF * NEMBD];
__device__ __nv_bfloat16 g_w2h[(size_t)NEXP * NEMBD * DFF];   // [e][N=NEMBD][K=DFF]
__device__ __nv_bfloat16 g_w2l[(size_t)NEXP * NEMBD * DFF];
__device__ __nv_bfloat16 g_hh[(size_t)NEXP * TOKENS * DFF];   // hidden hi
__device__ __nv_bfloat16 g_hl[(size_t)NEXP * TOKENS * DFF];   // hidden lo

// ---------------- helpers ----------------
__device__ __forceinline__ uint32_t smem_to_u32(const void* p) {
    uint32_t a;
    asm("{ .reg .u64 t; cvta.to.shared.u64 t, %1; cvt.u32.u64 %0, t; }" : "=r"(a) : "l"(p));
    return a;
}
__device__ __forceinline__ void cp_async16(uint32_t saddr, const void* gaddr) {
    asm volatile("cp.async.cg.shared.global [%0], [%1], 16;" :: "r"(saddr), "l"(gaddr));
}
#define CP_COMMIT() asm volatile("cp.async.commit_group;" ::: "memory")
#define CP_WAIT(n)  asm volatile("cp.async.wait_group %0;" :: "n"(n) : "memory")

__device__ __forceinline__ void ldsm_x4(uint32_t* r, uint32_t addr) {
    asm volatile("ldmatrix.sync.aligned.m8n8.x4.shared.b16 {%0,%1,%2,%3}, [%4];"
        : "=r"(r[0]), "=r"(r[1]), "=r"(r[2]), "=r"(r[3]) : "r"(addr));
}
__device__ __forceinline__ void mma_bf16(float* d, const uint32_t* a, const uint32_t* b) {
    asm volatile(
        "mma.sync.aligned.m16n8k16.row.col.f32.bf16.bf16.f32 "
        "{%0,%1,%2,%3}, {%4,%5,%6,%7}, {%8,%9}, {%0,%1,%2,%3};"
        : "+f"(d[0]), "+f"(d[1]), "+f"(d[2]), "+f"(d[3])
        : "r"(a[0]), "r"(a[1]), "r"(a[2]), "r"(a[3]), "r"(b[0]), "r"(b[1]));
}

__device__ __forceinline__ float gelu_exact(float x) {
    return 0.5f * x * (1.0f + erff(x * 0.70710678118654752440f));
}
__device__ __forceinline__ void split_bf16(float v, __nv_bfloat16& hi, __nv_bfloat16& lo) {
    hi = __float2bfloat16(v);
    lo = __float2bfloat16(v - __bfloat162float(hi));
}

// ---------------- pre-pass: convert x -> bf16 hi/lo ----------------
__global__ __launch_bounds__(256) void conv_split_x(const float* __restrict__ x) {
    const size_t n4 = (size_t)NEXP * TOKENS * NEMBD / 4;
    const float4* in = reinterpret_cast<const float4*>(x);
    for (size_t i = blockIdx.x * 256ull + threadIdx.x; i < n4; i += (size_t)gridDim.x * 256) {
        float4 v = in[i];
        __nv_bfloat16 h0, h1, h2, h3, l0, l1, l2, l3;
        split_bf16(v.x, h0, l0); split_bf16(v.y, h1, l1);
        split_bf16(v.z, h2, l2); split_bf16(v.w, h3, l3);
        __nv_bfloat162 ha = __halves2bfloat162(h0, h1), hb = __halves2bfloat162(h2, h3);
        __nv_bfloat162 la = __halves2bfloat162(l0, l1), lb = __halves2bfloat162(l2, l3);
        uint2 hv = make_uint2(*reinterpret_cast<uint32_t*>(&ha), *reinterpret_cast<uint32_t*>(&hb));
        uint2 lv = make_uint2(*reinterpret_cast<uint32_t*>(&la), *reinterpret_cast<uint32_t*>(&lb));
        reinterpret_cast<uint2*>(g_xh)[i] = hv;
        reinterpret_cast<uint2*>(g_xl)[i] = lv;
    }
}

// ---------------- pre-pass: convert + transpose weights ----------------
// W=1: c_fc [e][R=1024][C=4096] -> g_w1 [e][4096][1024]
// W=2: c_proj [e][R=4096][C=1024] -> g_w2 [e][1024][4096]
template<int W>
__global__ __launch_bounds__(256) void conv_transpose(const float* __restrict__ in) {
    constexpr int R = (W == 1) ? NEMBD : DFF;
    constexpr int C = (W == 1) ? DFF : NEMBD;
    __nv_bfloat16* oh = (W == 1) ? g_w1h : g_w2h;
    __nv_bfloat16* ol = (W == 1) ? g_w1l : g_w2l;
    __shared__ float t[32][33];
    const int e = blockIdx.z;
    const float* src = in + (size_t)e * R * C;
    __nv_bfloat16* dh = oh + (size_t)e * R * C;
    __nv_bfloat16* dl = ol + (size_t)e * R * C;
    const int c0 = blockIdx.x * 32, r0 = blockIdx.y * 32;
    const int tx = threadIdx.x & 31, ty = threadIdx.x >> 5;   // 32 x 8
    #pragma unroll
    for (int j = 0; j < 4; ++j)
        t[ty + j * 8][tx] = src[(size_t)(r0 + ty + j * 8) * C + c0 + tx];
    __syncthreads();
    #pragma unroll
    for (int j = 0; j < 4; ++j) {
        float v = t[tx][ty + j * 8];                     // in[r0+tx][c0+ty+j*8]
        __nv_bfloat16 hi, lo; split_bf16(v, hi, lo);
        size_t o = (size_t)(c0 + ty + j * 8) * R + r0 + tx;
        dh[o] = hi; dl[o] = lo;
    }
}

// ---------------- mma.sync grouped GEMM with bf16 hi/lo split ----------------
// C = A @ B^T(layout) where A:[M][K] (hi/lo), B:[N][K] (hi/lo), via
// a*b ~= ah*bh + ah*bl + al*bh  (error ~2^-18)
// DO_GELU=true : writes gelu(.+bias) as bf16 hi/lo into g_hh/g_hl
// DO_GELU=false: writes (.+bias) as fp32 into Cf
//
// SMEM stage: 4 tiles (Ah, Al, Bh, Bl), each 128 rows x 32 bf16, row stride 80B.
// 3 stages, cp.async pipeline.
template<bool DO_GELU>
__global__ __launch_bounds__(256, 1) void gemm_mma(const float* __restrict__ bias_all,
                                                   float* __restrict__ Cf) {
    constexpr int M = TOKENS;
    constexpr int N = DO_GELU ? DFF : NEMBD;
    constexpr int K = DO_GELU ? NEMBD : DFF;
    constexpr int NC = K / 32;          // k-chunks of 32
    constexpr int ROWB = 80;            // bytes per smem row (32 bf16 + 8 pad)
    constexpr int TILE = 128 * ROWB;    // 10240
    constexpr int STAGE = 4 * TILE;     // 40960

    const __nv_bfloat16* Ah = DO_GELU ? g_xh : g_hh;
    const __nv_bfloat16* Al = DO_GELU ? g_xl : g_hl;
    const __nv_bfloat16* Bh = DO_GELU ? g_w1h : g_w2h;
    const __nv_bfloat16* Bl = DO_GELU ? g_w1l : g_w2l;

    extern __shared__ __align__(1024) char smem[];
    const uint32_t sbase = smem_to_u32(smem);

    const int tid = threadIdx.x;
    const int wid = tid >> 5, lane = tid & 31;
    const int e = blockIdx.z;
    const int m0 = blockIdx.y * 128, n0 = blockIdx.x * 128;

    Ah += (size_t)e * M * K; Al += (size_t)e * M * K;
    Bh += (size_t)e * N * K; Bl += (size_t)e * N * K;
    const float* bias = bias_all + (size_t)e * N;

    // warp tile: 64(m) x 32(n); warps arranged 2(m) x 4(n)
    const int wm = (wid >> 2) * 64;
    const int wn = (wid & 3) * 32;

    float acc[4][4][4];
    #pragma unroll
    for (int i = 0; i < 4; ++i)
        #pragma unroll
        for (int j = 0; j < 4; ++j)
            #pragma unroll
            for (int q = 0; q < 4; ++q) acc[i][j][q] = 0.0f;

    // loader: chunk c -> stage s. 8 cp.async of 16B per thread.
    auto load_stage = [&](int c, int s) {
        const int kt = c * 32;
        const uint32_t sb = sbase + s * STAGE;
        #pragma unroll
        for (int it = 0; it < 2; ++it) {
            const int li  = tid + it * 256;
            const int row = li >> 2;
            const int ch  = li & 3;
            const uint32_t so = row * ROWB + ch * 16;
            const size_t  goA = (size_t)(m0 + row) * K + kt + ch * 8;
            const size_t  goB = (size_t)(n0 + row) * K + kt + ch * 8;
            cp_async16(sb            + so, Ah + goA);
            cp_async16(sb +     TILE + so, Al + goA);
            cp_async16(sb + 2 * TILE + so, Bh + goB);
            cp_async16(sb + 3 * TILE + so, Bl + goB);
        }
        CP_COMMIT();
    };

    load_stage(0, 0);
    load_stage(1, 1);

    // per-lane ldmatrix address components
    const uint32_t a_off = (uint32_t)((wm + (lane & 15)) * ROWB + (lane >> 4) * 16);
    const uint32_t b_off = (uint32_t)((wn + (lane & 7) + ((lane >> 4) << 3)) * ROWB + ((lane >> 3) & 1) * 16);

    for (int c = 0; c < NC; ++c) {
        if (c + 1 < NC) { CP_WAIT(1); } else { CP_WAIT(0); }
        __syncthreads();

        const uint32_t sb = sbase + (c % 3) * STAGE;
        #pragma unroll
        for (int ks = 0; ks < 2; ++ks) {
            const uint32_t kso = (uint32_t)(ks * 32);
            uint32_t afh[4][4], afl[4][4], bfh[2][4], bfl[2][4];
            #pragma unroll
            for (int mt = 0; mt < 4; ++mt) {
                const uint32_t ao = sb + a_off + kso + (uint32_t)(mt * 16 * ROWB);
                ldsm_x4(afh[mt], ao);
                ldsm_x4(afl[mt], ao + TILE);
            }
            #pragma unroll
            for (int nt2 = 0; nt2 < 2; ++nt2) {
                const uint32_t bo = sb + 2 * TILE + b_off + kso + (uint32_t)(nt2 * 16 * ROWB);
                ldsm_x4(bfh[nt2], bo);
                ldsm_x4(bfl[nt2], bo + TILE);
            }
            #pragma unroll
            for (int mt = 0; mt < 4; ++mt)
                #pragma unroll
                for (int nt = 0; nt < 4; ++nt) {
                    const uint32_t* bh = &bfh[nt >> 1][(nt & 1) * 2];
                    const uint32_t* bl = &bfl[nt >> 1][(nt & 1) * 2];
                    mma_bf16(acc[mt][nt], afh[mt], bh);
                    mma_bf16(acc[mt][nt], afh[mt], bl);
                    mma_bf16(acc[mt][nt], afl[mt], bh);
                }
        }
        __syncthreads();
        if (c + 2 < NC) load_stage(c + 2, (c + 2) % 3);
    }

    // ---------------- epilogue ----------------
    const int groupID = lane >> 2, tig = lane & 3;
    #pragma unroll
    for (int mt = 0; mt < 4; ++mt) {
        const int r0g = m0 + wm + mt * 16 + groupID;
        #pragma unroll
        for (int nt = 0; nt < 4; ++nt) {
            const int col = n0 + wn + nt * 8 + tig * 2;
            const float2 bv = *reinterpret_cast<const float2*>(&bias[col]);
            float v0 = acc[mt][nt][0] + bv.x;
            float v1 = acc[mt][nt][1] + bv.y;
            float v2 = acc[mt][nt][2] + bv.x;
            float v3 = acc[mt][nt][3] + bv.y;
            if (DO_GELU) {
                v0 = gelu_exact(v0); v1 = gelu_exact(v1);
                v2 = gelu_exact(v2); v3 = gelu_exact(v3);
                __nv_bfloat16 h0, l0, h1, l1, h2, l2, h3, l3;
                split_bf16(v0, h0, l0); split_bf16(v1, h1, l1);
                split_bf16(v2, h2, l2); split_bf16(v3, h3, l3);
                const size_t o0 = ((size_t)e * M + r0g) * N + col;
                const size_t o1 = ((size_t)e * M + r0g + 8) * N + col;
                *reinterpret_cast<__nv_bfloat162*>(g_hh + o0) = __halves2bfloat162(h0, h1);
                *reinterpret_cast<__nv_bfloat162*>(g_hl + o0) = __halves2bfloat162(l0, l1);
                *reinterpret_cast<__nv_bfloat162*>(g_hh + o1) = __halves2bfloat162(h2, h3);
                *reinterpret_cast<__nv_bfloat162*>(g_hl + o1) = __halves2bfloat162(l2, l3);
            } else {
                const size_t o0 = ((size_t)e * M + r0g) * N + col;
                const size_t o1 = ((size_t)e * M + r0g + 8) * N + col;
                *reinterpret_cast<float2*>(Cf + o0) = make_float2(v0, v1);
                *reinterpret_cast<float2*>(Cf + o1) = make_float2(v2, v3);
            }
        }
    }
}

// ---------------- launch ----------------
extern "C" void kernel_launch(void* const* d_in, const int* in_sizes, int n_in,
                              void* d_out, int out_size) {
    const float* x         = (const float*)d_in[0];
    const float* c_fc      = (const float*)d_in[1];
    const float* c_proj    = (const float*)d_in[2];
    const float* fc_bias   = (const float*)d_in[3];
    const float* proj_bias = (const float*)d_in[4];
    float* out = (float*)d_out;

    constexpr int SMEM_BYTES = 3 * 40960;   // 122880
    cudaFuncSetAttribute(gemm_mma<true>,  cudaFuncAttributeMaxDynamicSharedMemorySize, SMEM_BYTES);
    cudaFuncSetAttribute(gemm_mma<false>, cudaFuncAttributeMaxDynamicSharedMemorySize, SMEM_BYTES);

    // pre-passes
    conv_split_x<<<4096, 256>>>(x);
    conv_transpose<1><<<dim3(DFF / 32, NEMBD / 32, NEXP), 256>>>(c_fc);
    conv_transpose<2><<<dim3(NEMBD / 32, DFF / 32, NEXP), 256>>>(c_proj);

    // GEMM1: [2048,1024] @ [1024,4096] + b1, gelu -> h (bf16 hi/lo)
    gemm_mma<true><<<dim3(DFF / 128, TOKENS / 128, NEXP), 256, SMEM_BYTES>>>(fc_bias, nullptr);
    // GEMM2: [2048,4096] @ [4096,1024] + b2 -> out (fp32)
    gemm_mma<false><<<dim3(NEMBD / 128, TOKENS / 128, NEXP), 256, SMEM_BYTES>>>(proj_bias, out);
}

// round 4
// speedup vs baseline: 2.2180x; 1.0438x over previous
#include <cuda_runtime.h>
#include <cuda_bf16.h>
#include <math.h>
#include <stdint.h>

#define NEXP   8
#define TOKENS 2048
#define NEMBD  1024
#define DFF    4096

// ---------------- device scratch (no runtime allocation) ----------------
__device__ __nv_bfloat16 g_xh[(size_t)NEXP * TOKENS * NEMBD];
__device__ __nv_bfloat16 g_xl[(size_t)NEXP * TOKENS * NEMBD];
__device__ __nv_bfloat16 g_w1h[(size_t)NEXP * DFF * NEMBD];   // [e][N=DFF][K=NEMBD]
__device__ __nv_bfloat16 g_w1l[(size_t)NEXP * DFF * NEMBD];
__device__ __nv_bfloat16 g_w2h[(size_t)NEXP * NEMBD * DFF];   // [e][N=NEMBD][K=DFF]
__device__ __nv_bfloat16 g_w2l[(size_t)NEXP * NEMBD * DFF];
__device__ __nv_bfloat16 g_hh[(size_t)NEXP * TOKENS * DFF];   // hidden hi
__device__ __nv_bfloat16 g_hl[(size_t)NEXP * TOKENS * DFF];   // hidden lo

// ---------------- helpers ----------------
__device__ __forceinline__ uint32_t smem_to_u32(const void* p) {
    uint32_t a;
    asm("{ .reg .u64 t; cvta.to.shared.u64 t, %1; cvt.u32.u64 %0, t; }" : "=r"(a) : "l"(p));
    return a;
}
__device__ __forceinline__ void cp_async16(uint32_t saddr, const void* gaddr) {
    asm volatile("cp.async.cg.shared.global [%0], [%1], 16;" :: "r"(saddr), "l"(gaddr));
}
#define CP_COMMIT() asm volatile("cp.async.commit_group;" ::: "memory")
#define CP_WAIT(n)  asm volatile("cp.async.wait_group %0;" :: "n"(n) : "memory")

__device__ __forceinline__ void ldsm_x4(uint32_t* r, uint32_t addr) {
    asm volatile("ldmatrix.sync.aligned.m8n8.x4.shared.b16 {%0,%1,%2,%3}, [%4];"
        : "=r"(r[0]), "=r"(r[1]), "=r"(r[2]), "=r"(r[3]) : "r"(addr));
}
__device__ __forceinline__ void mma_bf16(float* d, const uint32_t* a, const uint32_t* b) {
    asm volatile(
        "mma.sync.aligned.m16n8k16.row.col.f32.bf16.bf16.f32 "
        "{%0,%1,%2,%3}, {%4,%5,%6,%7}, {%8,%9}, {%0,%1,%2,%3};"
        : "+f"(d[0]), "+f"(d[1]), "+f"(d[2]), "+f"(d[3])
        : "r"(a[0]), "r"(a[1]), "r"(a[2]), "r"(a[3]), "r"(b[0]), "r"(b[1]));
}

__device__ __forceinline__ float gelu_exact(float x) {
    return 0.5f * x * (1.0f + erff(x * 0.70710678118654752440f));
}
__device__ __forceinline__ void split_bf16(float v, __nv_bfloat16& hi, __nv_bfloat16& lo) {
    hi = __float2bfloat16(v);
    lo = __float2bfloat16(v - __bfloat162float(hi));
}

// ---------------- pre-pass: convert x -> bf16 hi/lo ----------------
__global__ __launch_bounds__(256) void conv_split_x(const float* __restrict__ x) {
    const size_t n4 = (size_t)NEXP * TOKENS * NEMBD / 4;
    const float4* in = reinterpret_cast<const float4*>(x);
    for (size_t i = blockIdx.x * 256ull + threadIdx.x; i < n4; i += (size_t)gridDim.x * 256) {
        float4 v = in[i];
        __nv_bfloat16 h0, h1, h2, h3, l0, l1, l2, l3;
        split_bf16(v.x, h0, l0); split_bf16(v.y, h1, l1);
        split_bf16(v.z, h2, l2); split_bf16(v.w, h3, l3);
        __nv_bfloat162 ha = __halves2bfloat162(h0, h1), hb = __halves2bfloat162(h2, h3);
        __nv_bfloat162 la = __halves2bfloat162(l0, l1), lb = __halves2bfloat162(l2, l3);
        uint2 hv = make_uint2(*reinterpret_cast<uint32_t*>(&ha), *reinterpret_cast<uint32_t*>(&hb));
        uint2 lv = make_uint2(*reinterpret_cast<uint32_t*>(&la), *reinterpret_cast<uint32_t*>(&lb));
        reinterpret_cast<uint2*>(g_xh)[i] = hv;
        reinterpret_cast<uint2*>(g_xl)[i] = lv;
    }
}

// ---------------- pre-pass: convert + transpose weights ----------------
template<int W>
__global__ __launch_bounds__(256) void conv_transpose(const float* __restrict__ in) {
    constexpr int R = (W == 1) ? NEMBD : DFF;
    constexpr int C = (W == 1) ? DFF : NEMBD;
    __nv_bfloat16* oh = (W == 1) ? g_w1h : g_w2h;
    __nv_bfloat16* ol = (W == 1) ? g_w1l : g_w2l;
    __shared__ float t[32][33];
    const int e = blockIdx.z;
    const float* src = in + (size_t)e * R * C;
    __nv_bfloat16* dh = oh + (size_t)e * R * C;
    __nv_bfloat16* dl = ol + (size_t)e * R * C;
    const int c0 = blockIdx.x * 32, r0 = blockIdx.y * 32;
    const int tx = threadIdx.x & 31, ty = threadIdx.x >> 5;   // 32 x 8
    #pragma unroll
    for (int j = 0; j < 4; ++j)
        t[ty + j * 8][tx] = src[(size_t)(r0 + ty + j * 8) * C + c0 + tx];
    __syncthreads();
    #pragma unroll
    for (int j = 0; j < 4; ++j) {
        float v = t[tx][ty + j * 8];                     // in[r0+tx][c0+ty+j*8]
        __nv_bfloat16 hi, lo; split_bf16(v, hi, lo);
        size_t o = (size_t)(c0 + ty + j * 8) * R + r0 + tx;
        dh[o] = hi; dl[o] = lo;
    }
}

// ---------------- mma.sync grouped GEMM with bf16 hi/lo split ----------------
// CTA tile 256(m) x 128(n), BK=32, 8 warps as 4(m) x 2(n), warp tile 64x64.
// a*b ~= ah*bh + ah*bl + al*bh  (3 MMA terms, residual ~2^-18)
template<bool DO_GELU>
__global__ __launch_bounds__(256, 1) void gemm_mma(const float* __restrict__ bias_all,
                                                   float* __restrict__ Cf) {
    constexpr int M = TOKENS;
    constexpr int N = DO_GELU ? DFF : NEMBD;
    constexpr int K = DO_GELU ? NEMBD : DFF;
    constexpr int NC = K / 32;             // k-chunks of 32
    constexpr int ROWB = 80;               // bytes per smem row (32 bf16 + 8 pad)
    constexpr int A_TILE = 256 * ROWB;     // 20480
    constexpr int B_TILE = 128 * ROWB;     // 10240
    constexpr int STAGE = 2 * A_TILE + 2 * B_TILE;   // 61440 (Ah, Al, Bh, Bl)

    const __nv_bfloat16* Ah = DO_GELU ? g_xh : g_hh;
    const __nv_bfloat16* Al = DO_GELU ? g_xl : g_hl;
    const __nv_bfloat16* Bh = DO_GELU ? g_w1h : g_w2h;
    const __nv_bfloat16* Bl = DO_GELU ? g_w1l : g_w2l;

    extern __shared__ __align__(1024) char smem[];
    const uint32_t sbase = smem_to_u32(smem);

    const int tid = threadIdx.x;
    const int wid = tid >> 5, lane = tid & 31;
    const int e = blockIdx.z;
    const int m0 = blockIdx.y * 256, n0 = blockIdx.x * 128;

    Ah += (size_t)e * M * K; Al += (size_t)e * M * K;
    Bh += (size_t)e * N * K; Bl += (size_t)e * N * K;
    const float* bias = bias_all + (size_t)e * N;

    // warp tile: 64(m) x 64(n); warps arranged 4(m) x 2(n)
    const int wm = (wid >> 1) * 64;
    const int wn = (wid & 1) * 64;

    float acc[4][8][4];
    #pragma unroll
    for (int i = 0; i < 4; ++i)
        #pragma unroll
        for (int j = 0; j < 8; ++j)
            #pragma unroll
            for (int q = 0; q < 4; ++q) acc[i][j][q] = 0.0f;

    // loader: chunk c -> stage s. 12 cp.async of 16B per thread.
    auto load_stage = [&](int c, int s) {
        const int kt = c * 32;
        const uint32_t sb = sbase + s * STAGE;
        #pragma unroll
        for (int it = 0; it < 4; ++it) {          // A: 256 rows x 4 chunks
            const int li  = tid + it * 256;
            const int row = li >> 2;
            const int ch  = li & 3;
            const uint32_t so = row * ROWB + ch * 16;
            const size_t  go = (size_t)(m0 + row) * K + kt + ch * 8;
            cp_async16(sb          + so, Ah + go);
            cp_async16(sb + A_TILE + so, Al + go);
        }
        #pragma unroll
        for (int it = 0; it < 2; ++it) {          // B: 128 rows x 4 chunks
            const int li  = tid + it * 256;
            const int row = li >> 2;
            const int ch  = li & 3;
            const uint32_t so = row * ROWB + ch * 16;
            const size_t  go = (size_t)(n0 + row) * K + kt + ch * 8;
            cp_async16(sb + 2 * A_TILE          + so, Bh + go);
            cp_async16(sb + 2 * A_TILE + B_TILE + so, Bl + go);
        }
        CP_COMMIT();
    };

    load_stage(0, 0);
    load_stage(1, 1);

    // per-lane ldmatrix address components
    const uint32_t a_off = (uint32_t)((wm + (lane & 15)) * ROWB + (lane >> 4) * 16);
    const uint32_t b_off = (uint32_t)((wn + (lane & 7) + ((lane >> 4) << 3)) * ROWB + ((lane >> 3) & 1) * 16);

    for (int c = 0; c < NC; ++c) {
        if (c + 1 < NC) { CP_WAIT(1); } else { CP_WAIT(0); }
        __syncthreads();

        const uint32_t sb = sbase + (c % 3) * STAGE;
        #pragma unroll
        for (int ks = 0; ks < 2; ++ks) {
            const uint32_t kso = (uint32_t)(ks * 32);
            uint32_t bfh[4][4], bfl[4][4];
            #pragma unroll
            for (int nt2 = 0; nt2 < 4; ++nt2) {
                const uint32_t bo = sb + 2 * A_TILE + b_off + kso + (uint32_t)(nt2 * 16 * ROWB);
                ldsm_x4(bfh[nt2], bo);
                ldsm_x4(bfl[nt2], bo + B_TILE);
            }
            #pragma unroll
            for (int mt = 0; mt < 4; ++mt) {
                uint32_t afh[4], afl[4];
                const uint32_t ao = sb + a_off + kso + (uint32_t)(mt * 16 * ROWB);
                ldsm_x4(afh, ao);
                ldsm_x4(afl, ao + A_TILE);
                #pragma unroll
                for (int nt = 0; nt < 8; ++nt) {
                    const uint32_t* bh = &bfh[nt >> 1][(nt & 1) * 2];
                    const uint32_t* bl = &bfl[nt >> 1][(nt & 1) * 2];
                    mma_bf16(acc[mt][nt], afh, bh);
                    mma_bf16(acc[mt][nt], afh, bl);
                    mma_bf16(acc[mt][nt], afl, bh);
                }
            }
        }
        __syncthreads();
        if (c + 2 < NC) load_stage(c + 2, (c + 2) % 3);
    }

    // ---------------- epilogue ----------------
    const int groupID = lane >> 2, tig = lane & 3;
    #pragma unroll
    for (int mt = 0; mt < 4; ++mt) {
        const int r0g = m0 + wm + mt * 16 + groupID;
        #pragma unroll
        for (int nt = 0; nt < 8; ++nt) {
            const int col = n0 + wn + nt * 8 + tig * 2;
            const float2 bv = *reinterpret_cast<const float2*>(&bias[col]);
            float v0 = acc[mt][nt][0] + bv.x;
            float v1 = acc[mt][nt][1] + bv.y;
            float v2 = acc[mt][nt][2] + bv.x;
            float v3 = acc[mt][nt][3] + bv.y;
            if (DO_GELU) {
                v0 = gelu_exact(v0); v1 = gelu_exact(v1);
                v2 = gelu_exact(v2); v3 = gelu_exact(v3);
                __nv_bfloat16 h0, l0, h1, l1, h2, l2, h3, l3;
                split_bf16(v0, h0, l0); split_bf16(v1, h1, l1);
                split_bf16(v2, h2, l2); split_bf16(v3, h3, l3);
                const size_t o0 = ((size_t)e * M + r0g) * N + col;
                const size_t o1 = ((size_t)e * M + r0g + 8) * N + col;
                *reinterpret_cast<__nv_bfloat162*>(g_hh + o0) = __halves2bfloat162(h0, h1);
                *reinterpret_cast<__nv_bfloat162*>(g_hl + o0) = __halves2bfloat162(l0, l1);
                *reinterpret_cast<__nv_bfloat162*>(g_hh + o1) = __halves2bfloat162(h2, h3);
                *reinterpret_cast<__nv_bfloat162*>(g_hl + o1) = __halves2bfloat162(l2, l3);
            } else {
                const size_t o0 = ((size_t)e * M + r0g) * N + col;
                const size_t o1 = ((size_t)e * M + r0g + 8) * N + col;
                *reinterpret_cast<float2*>(Cf + o0) = make_float2(v0, v1);
                *reinterpret_cast<float2*>(Cf + o1) = make_float2(v2, v3);
            }
        }
    }
}

// ---------------- launch ----------------
extern "C" void kernel_launch(void* const* d_in, const int* in_sizes, int n_in,
                              void* d_out, int out_size) {
    const float* x         = (const float*)d_in[0];
    const float* c_fc      = (const float*)d_in[1];
    const float* c_proj    = (const float*)d_in[2];
    const float* fc_bias   = (const float*)d_in[3];
    const float* proj_bias = (const float*)d_in[4];
    float* out = (float*)d_out;

    constexpr int SMEM_BYTES = 3 * 61440;   // 184320
    cudaFuncSetAttribute(gemm_mma<true>,  cudaFuncAttributeMaxDynamicSharedMemorySize, SMEM_BYTES);
    cudaFuncSetAttribute(gemm_mma<false>, cudaFuncAttributeMaxDynamicSharedMemorySize, SMEM_BYTES);

    // pre-passes
    conv_split_x<<<4096, 256>>>(x);
    conv_transpose<1><<<dim3(DFF / 32, NEMBD / 32, NEXP), 256>>>(c_fc);
    conv_transpose<2><<<dim3(NEMBD / 32, DFF / 32, NEXP), 256>>>(c_proj);

    // GEMM1: [2048,1024] @ [1024,4096] + b1, gelu -> h (bf16 hi/lo)
    gemm_mma<true><<<dim3(DFF / 128, TOKENS / 256, NEXP), 256, SMEM_BYTES>>>(fc_bias, nullptr);
    // GEMM2: [2048,4096] @ [4096,1024] + b2 -> out (fp32)
    gemm_mma<false><<<dim3(NEMBD / 128, TOKENS / 256, NEXP), 256, SMEM_BYTES>>>(proj_bias, out);
}

// round 5
// speedup vs baseline: 2.2326x; 1.0066x over previous
#include <cuda_runtime.h>
#include <cuda_bf16.h>
#include <math.h>
#include <stdint.h>

#define NEXP   8
#define TOKENS 2048
#define NEMBD  1024
#define DFF    4096

// ---------------- device scratch (no runtime allocation) ----------------
__device__ __nv_bfloat16 g_xh[(size_t)NEXP * TOKENS * NEMBD];
__device__ __nv_bfloat16 g_xl[(size_t)NEXP * TOKENS * NEMBD];
__device__ __nv_bfloat16 g_w1h[(size_t)NEXP * DFF * NEMBD];   // [e][N=DFF][K=NEMBD]
__device__ __nv_bfloat16 g_w1l[(size_t)NEXP * DFF * NEMBD];
__device__ __nv_bfloat16 g_w2h[(size_t)NEXP * NEMBD * DFF];   // [e][N=NEMBD][K=DFF]
__device__ __nv_bfloat16 g_w2l[(size_t)NEXP * NEMBD * DFF];
__device__ __nv_bfloat16 g_hh[(size_t)NEXP * TOKENS * DFF];   // hidden hi
__device__ __nv_bfloat16 g_hl[(size_t)NEXP * TOKENS * DFF];   // hidden lo

// ---------------- helpers ----------------
__device__ __forceinline__ uint32_t smem_to_u32(const void* p) {
    uint32_t a;
    asm("{ .reg .u64 t; cvta.to.shared.u64 t, %1; cvt.u32.u64 %0, t; }" : "=r"(a) : "l"(p));
    return a;
}
__device__ __forceinline__ void cp_async16(uint32_t saddr, const void* gaddr) {
    asm volatile("cp.async.cg.shared.global [%0], [%1], 16;" :: "r"(saddr), "l"(gaddr));
}
#define CP_COMMIT() asm volatile("cp.async.commit_group;" ::: "memory")
#define CP_WAIT(n)  asm volatile("cp.async.wait_group %0;" :: "n"(n) : "memory")

__device__ __forceinline__ void ldsm_x4(uint32_t* r, uint32_t addr) {
    asm volatile("ldmatrix.sync.aligned.m8n8.x4.shared.b16 {%0,%1,%2,%3}, [%4];"
        : "=r"(r[0]), "=r"(r[1]), "=r"(r[2]), "=r"(r[3]) : "r"(addr));
}
__device__ __forceinline__ void mma_bf16(float* d, const uint32_t* a, const uint32_t* b) {
    asm volatile(
        "mma.sync.aligned.m16n8k16.row.col.f32.bf16.bf16.f32 "
        "{%0,%1,%2,%3}, {%4,%5,%6,%7}, {%8,%9}, {%0,%1,%2,%3};"
        : "+f"(d[0]), "+f"(d[1]), "+f"(d[2]), "+f"(d[3])
        : "r"(a[0]), "r"(a[1]), "r"(a[2]), "r"(a[3]), "r"(b[0]), "r"(b[1]));
}

__device__ __forceinline__ float gelu_exact(float x) {
    return 0.5f * x * (1.0f + erff(x * 0.70710678118654752440f));
}
__device__ __forceinline__ void split_bf16(float v, __nv_bfloat16& hi, __nv_bfloat16& lo) {
    hi = __float2bfloat16(v);
    lo = __float2bfloat16(v - __bfloat162float(hi));
}

// ---------------- pre-pass: convert x -> bf16 hi/lo ----------------
__global__ __launch_bounds__(256) void conv_split_x(const float* __restrict__ x) {
    const size_t n4 = (size_t)NEXP * TOKENS * NEMBD / 4;
    const float4* in = reinterpret_cast<const float4*>(x);
    for (size_t i = blockIdx.x * 256ull + threadIdx.x; i < n4; i += (size_t)gridDim.x * 256) {
        float4 v = in[i];
        __nv_bfloat16 h0, h1, h2, h3, l0, l1, l2, l3;
        split_bf16(v.x, h0, l0); split_bf16(v.y, h1, l1);
        split_bf16(v.z, h2, l2); split_bf16(v.w, h3, l3);
        __nv_bfloat162 ha = __halves2bfloat162(h0, h1), hb = __halves2bfloat162(h2, h3);
        __nv_bfloat162 la = __halves2bfloat162(l0, l1), lb = __halves2bfloat162(l2, l3);
        uint2 hv = make_uint2(*reinterpret_cast<uint32_t*>(&ha), *reinterpret_cast<uint32_t*>(&hb));
        uint2 lv = make_uint2(*reinterpret_cast<uint32_t*>(&la), *reinterpret_cast<uint32_t*>(&lb));
        reinterpret_cast<uint2*>(g_xh)[i] = hv;
        reinterpret_cast<uint2*>(g_xl)[i] = lv;
    }
}

// ---------------- pre-pass: convert + transpose weights ----------------
template<int W>
__global__ __launch_bounds__(256) void conv_transpose(const float* __restrict__ in) {
    constexpr int R = (W == 1) ? NEMBD : DFF;
    constexpr int C = (W == 1) ? DFF : NEMBD;
    __nv_bfloat16* oh = (W == 1) ? g_w1h : g_w2h;
    __nv_bfloat16* ol = (W == 1) ? g_w1l : g_w2l;
    __shared__ float t[32][33];
    const int e = blockIdx.z;
    const float* src = in + (size_t)e * R * C;
    __nv_bfloat16* dh = oh + (size_t)e * R * C;
    __nv_bfloat16* dl = ol + (size_t)e * R * C;
    const int c0 = blockIdx.x * 32, r0 = blockIdx.y * 32;
    const int tx = threadIdx.x & 31, ty = threadIdx.x >> 5;   // 32 x 8
    #pragma unroll
    for (int j = 0; j < 4; ++j)
        t[ty + j * 8][tx] = src[(size_t)(r0 + ty + j * 8) * C + c0 + tx];
    __syncthreads();
    #pragma unroll
    for (int j = 0; j < 4; ++j) {
        float v = t[tx][ty + j * 8];                     // in[r0+tx][c0+ty+j*8]
        __nv_bfloat16 hi, lo; split_bf16(v, hi, lo);
        size_t o = (size_t)(c0 + ty + j * 8) * R + r0 + tx;
        dh[o] = hi; dl[o] = lo;
    }
}

// ---------------- mma.sync grouped GEMM with bf16 hi/lo split ----------------
// CTA tile 256(m) x 128(n), BK=32, 8 warps as 4(m) x 2(n), warp tile 64x64.
// a*b ~= ah*bh + ah*bl + al*bh  (3 MMA terms, residual ~2^-18)
// MMA terms are issued in nt-major order so same-accumulator reuse distance is 8.
template<bool DO_GELU>
__global__ __launch_bounds__(256, 1) void gemm_mma(const float* __restrict__ bias_all,
                                                   float* __restrict__ Cf) {
    constexpr int M = TOKENS;
    constexpr int N = DO_GELU ? DFF : NEMBD;
    constexpr int K = DO_GELU ? NEMBD : DFF;
    constexpr int NC = K / 32;             // k-chunks of 32
    constexpr int ROWB = 80;               // bytes per smem row (32 bf16 + 8 pad)
    constexpr int A_TILE = 256 * ROWB;     // 20480
    constexpr int B_TILE = 128 * ROWB;     // 10240
    constexpr int STAGE = 2 * A_TILE + 2 * B_TILE;   // 61440 (Ah, Al, Bh, Bl)

    const __nv_bfloat16* Ah = DO_GELU ? g_xh : g_hh;
    const __nv_bfloat16* Al = DO_GELU ? g_xl : g_hl;
    const __nv_bfloat16* Bh = DO_GELU ? g_w1h : g_w2h;
    const __nv_bfloat16* Bl = DO_GELU ? g_w1l : g_w2l;

    extern __shared__ __align__(1024) char smem[];
    const uint32_t sbase = smem_to_u32(smem);

    const int tid = threadIdx.x;
    const int wid = tid >> 5, lane = tid & 31;
    const int e = blockIdx.z;
    const int m0 = blockIdx.y * 256, n0 = blockIdx.x * 128;

    Ah += (size_t)e * M * K; Al += (size_t)e * M * K;
    Bh += (size_t)e * N * K; Bl += (size_t)e * N * K;
    const float* bias = bias_all + (size_t)e * N;

    // warp tile: 64(m) x 64(n); warps arranged 4(m) x 2(n)
    const int wm = (wid >> 1) * 64;
    const int wn = (wid & 1) * 64;

    float acc[4][8][4];
    #pragma unroll
    for (int i = 0; i < 4; ++i)
        #pragma unroll
        for (int j = 0; j < 8; ++j)
            #pragma unroll
            for (int q = 0; q < 4; ++q) acc[i][j][q] = 0.0f;

    // loader: chunk c -> stage s. 12 cp.async of 16B per thread.
    auto load_stage = [&](int c, int s) {
        const int kt = c * 32;
        const uint32_t sb = sbase + s * STAGE;
        #pragma unroll
        for (int it = 0; it < 4; ++it) {          // A: 256 rows x 4 chunks
            const int li  = tid + it * 256;
            const int row = li >> 2;
            const int ch  = li & 3;
            const uint32_t so = row * ROWB + ch * 16;
            const size_t  go = (size_t)(m0 + row) * K + kt + ch * 8;
            cp_async16(sb          + so, Ah + go);
            cp_async16(sb + A_TILE + so, Al + go);
        }
        #pragma unroll
        for (int it = 0; it < 2; ++it) {          // B: 128 rows x 4 chunks
            const int li  = tid + it * 256;
            const int row = li >> 2;
            const int ch  = li & 3;
            const uint32_t so = row * ROWB + ch * 16;
            const size_t  go = (size_t)(n0 + row) * K + kt + ch * 8;
            cp_async16(sb + 2 * A_TILE          + so, Bh + go);
            cp_async16(sb + 2 * A_TILE + B_TILE + so, Bl + go);
        }
        CP_COMMIT();
    };

    load_stage(0, 0);
    load_stage(1, 1);

    // per-lane ldmatrix address components
    const uint32_t a_off = (uint32_t)((wm + (lane & 15)) * ROWB + (lane >> 4) * 16);
    const uint32_t b_off = (uint32_t)((wn + (lane & 7) + ((lane >> 4) << 3)) * ROWB + ((lane >> 3) & 1) * 16);

    for (int c = 0; c < NC; ++c) {
        // wait for chunk c data, one barrier per iteration
        if (c + 1 < NC) { CP_WAIT(1); } else { CP_WAIT(0); }
        __syncthreads();
        // stage (c+2)%3 == (c-1)%3 was last read in iteration c-1, before this barrier
        if (c + 2 < NC) load_stage(c + 2, (c + 2) % 3);

        const uint32_t sb = sbase + (c % 3) * STAGE;
        #pragma unroll
        for (int ks = 0; ks < 2; ++ks) {
            const uint32_t kso = (uint32_t)(ks * 32);
            uint32_t bfh[4][4], bfl[4][4];
            #pragma unroll
            for (int nt2 = 0; nt2 < 4; ++nt2) {
                const uint32_t bo = sb + 2 * A_TILE + b_off + kso + (uint32_t)(nt2 * 16 * ROWB);
                ldsm_x4(bfh[nt2], bo);
                ldsm_x4(bfl[nt2], bo + B_TILE);
            }
            #pragma unroll
            for (int mt = 0; mt < 4; ++mt) {
                uint32_t afh[4], afl[4];
                const uint32_t ao = sb + a_off + kso + (uint32_t)(mt * 16 * ROWB);
                ldsm_x4(afh, ao);
                ldsm_x4(afl, ao + A_TILE);
                // term 1: ah*bh — 8 independent MMAs
                #pragma unroll
                for (int nt = 0; nt < 8; ++nt)
                    mma_bf16(acc[mt][nt], afh, &bfh[nt >> 1][(nt & 1) * 2]);
                // term 2: ah*bl
                #pragma unroll
                for (int nt = 0; nt < 8; ++nt)
                    mma_bf16(acc[mt][nt], afh, &bfl[nt >> 1][(nt & 1) * 2]);
                // term 3: al*bh
                #pragma unroll
                for (int nt = 0; nt < 8; ++nt)
                    mma_bf16(acc[mt][nt], afl, &bfh[nt >> 1][(nt & 1) * 2]);
            }
        }
    }

    // ---------------- epilogue ----------------
    const int groupID = lane >> 2, tig = lane & 3;
    #pragma unroll
    for (int mt = 0; mt < 4; ++mt) {
        const int r0g = m0 + wm + mt * 16 + groupID;
        #pragma unroll
        for (int nt = 0; nt < 8; ++nt) {
            const int col = n0 + wn + nt * 8 + tig * 2;
            const float2 bv = *reinterpret_cast<const float2*>(&bias[col]);
            float v0 = acc[mt][nt][0] + bv.x;
            float v1 = acc[mt][nt][1] + bv.y;
            float v2 = acc[mt][nt][2] + bv.x;
            float v3 = acc[mt][nt][3] + bv.y;
            if (DO_GELU) {
                v0 = gelu_exact(v0); v1 = gelu_exact(v1);
                v2 = gelu_exact(v2); v3 = gelu_exact(v3);
                __nv_bfloat16 h0, l0, h1, l1, h2, l2, h3, l3;
                split_bf16(v0, h0, l0); split_bf16(v1, h1, l1);
                split_bf16(v2, h2, l2); split_bf16(v3, h3, l3);
                const size_t o0 = ((size_t)e * M + r0g) * N + col;
                const size_t o1 = ((size_t)e * M + r0g + 8) * N + col;
                *reinterpret_cast<__nv_bfloat162*>(g_hh + o0) = __halves2bfloat162(h0, h1);
                *reinterpret_cast<__nv_bfloat162*>(g_hl + o0) = __halves2bfloat162(l0, l1);
                *reinterpret_cast<__nv_bfloat162*>(g_hh + o1) = __halves2bfloat162(h2, h3);
                *reinterpret_cast<__nv_bfloat162*>(g_hl + o1) = __halves2bfloat162(l2, l3);
            } else {
                const size_t o0 = ((size_t)e * M + r0g) * N + col;
                const size_t o1 = ((size_t)e * M + r0g + 8) * N + col;
                *reinterpret_cast<float2*>(Cf + o0) = make_float2(v0, v1);
                *reinterpret_cast<float2*>(Cf + o1) = make_float2(v2, v3);
            }
        }
    }
}

// ---------------- launch ----------------
extern "C" void kernel_launch(void* const* d_in, const int* in_sizes, int n_in,
                              void* d_out, int out_size) {
    const float* x         = (const float*)d_in[0];
    const float* c_fc      = (const float*)d_in[1];
    const float* c_proj    = (const float*)d_in[2];
    const float* fc_bias   = (const float*)d_in[3];
    const float* proj_bias = (const float*)d_in[4];
    float* out = (float*)d_out;

    constexpr int SMEM_BYTES = 3 * 61440;   // 184320
    cudaFuncSetAttribute(gemm_mma<true>,  cudaFuncAttributeMaxDynamicSharedMemorySize, SMEM_BYTES);
    cudaFuncSetAttribute(gemm_mma<false>, cudaFuncAttributeMaxDynamicSharedMemorySize, SMEM_BYTES);

    // pre-passes
    conv_split_x<<<4096, 256>>>(x);
    conv_transpose<1><<<dim3(DFF / 32, NEMBD / 32, NEXP), 256>>>(c_fc);
    conv_transpose<2><<<dim3(NEMBD / 32, DFF / 32, NEXP), 256>>>(c_proj);

    // GEMM1: [2048,1024] @ [1024,4096] + b1, gelu -> h (bf16 hi/lo)
    gemm_mma<true><<<dim3(DFF / 128, TOKENS / 256, NEXP), 256, SMEM_BYTES>>>(fc_bias, nullptr);
    // GEMM2: [2048,4096] @ [4096,1024] + b2 -> out (fp32)
    gemm_mma<false><<<dim3(NEMBD / 128, TOKENS / 256, NEXP), 256, SMEM_BYTES>>>(proj_bias, out);
}

// round 6
// speedup vs baseline: 2.3552x; 1.0549x over previous
#include <cuda_runtime.h>
#include <cuda_bf16.h>
#include <math.h>
#include <stdint.h>

#define NEXP   8
#define TOKENS 2048
#define NEMBD  1024
#define DFF    4096

// ---------------- device scratch (no runtime allocation) ----------------
__device__ __nv_bfloat16 g_xh[(size_t)NEXP * TOKENS * NEMBD];
__device__ __nv_bfloat16 g_xl[(size_t)NEXP * TOKENS * NEMBD];
__device__ __nv_bfloat16 g_w1h[(size_t)NEXP * DFF * NEMBD];   // [e][N=DFF][K=NEMBD]
__device__ __nv_bfloat16 g_w1l[(size_t)NEXP * DFF * NEMBD];
__device__ __nv_bfloat16 g_w2h[(size_t)NEXP * NEMBD * DFF];   // [e][N=NEMBD][K=DFF]
__device__ __nv_bfloat16 g_w2l[(size_t)NEXP * NEMBD * DFF];
__device__ __nv_bfloat16 g_hh[(size_t)NEXP * TOKENS * DFF];   // hidden hi
__device__ __nv_bfloat16 g_hl[(size_t)NEXP * TOKENS * DFF];   // hidden lo

// ---------------- helpers ----------------
__device__ __forceinline__ uint32_t smem_to_u32(const void* p) {
    uint32_t a;
    asm("{ .reg .u64 t; cvta.to.shared.u64 t, %1; cvt.u32.u64 %0, t; }" : "=r"(a) : "l"(p));
    return a;
}
__device__ __forceinline__ void cp_async16(uint32_t saddr, const void* gaddr) {
    asm volatile("cp.async.cg.shared.global [%0], [%1], 16;" :: "r"(saddr), "l"(gaddr));
}
#define CP_COMMIT() asm volatile("cp.async.commit_group;" ::: "memory")
#define CP_WAIT(n)  asm volatile("cp.async.wait_group %0;" :: "n"(n) : "memory")

__device__ __forceinline__ void ldsm_x4(uint32_t* r, uint32_t addr) {
    asm volatile("ldmatrix.sync.aligned.m8n8.x4.shared.b16 {%0,%1,%2,%3}, [%4];"
        : "=r"(r[0]), "=r"(r[1]), "=r"(r[2]), "=r"(r[3]) : "r"(addr));
}
__device__ __forceinline__ void mma_bf16(float* d, const uint32_t* a, const uint32_t* b) {
    asm volatile(
        "mma.sync.aligned.m16n8k16.row.col.f32.bf16.bf16.f32 "
        "{%0,%1,%2,%3}, {%4,%5,%6,%7}, {%8,%9}, {%0,%1,%2,%3};"
        : "+f"(d[0]), "+f"(d[1]), "+f"(d[2]), "+f"(d[3])
        : "r"(a[0]), "r"(a[1]), "r"(a[2]), "r"(a[3]), "r"(b[0]), "r"(b[1]));
}

__device__ __forceinline__ float gelu_exact(float x) {
    return 0.5f * x * (1.0f + erff(x * 0.70710678118654752440f));
}
__device__ __forceinline__ void split_bf16(float v, __nv_bfloat16& hi, __nv_bfloat16& lo) {
    hi = __float2bfloat16(v);
    lo = __float2bfloat16(v - __bfloat162float(hi));
}

// ---------------- pre-pass: convert x -> bf16 hi/lo ----------------
__global__ __launch_bounds__(256) void conv_split_x(const float* __restrict__ x) {
    const size_t n4 = (size_t)NEXP * TOKENS * NEMBD / 4;
    const float4* in = reinterpret_cast<const float4*>(x);
    for (size_t i = blockIdx.x * 256ull + threadIdx.x; i < n4; i += (size_t)gridDim.x * 256) {
        float4 v = in[i];
        __nv_bfloat16 h0, h1, h2, h3, l0, l1, l2, l3;
        split_bf16(v.x, h0, l0); split_bf16(v.y, h1, l1);
        split_bf16(v.z, h2, l2); split_bf16(v.w, h3, l3);
        __nv_bfloat162 ha = __halves2bfloat162(h0, h1), hb = __halves2bfloat162(h2, h3);
        __nv_bfloat162 la = __halves2bfloat162(l0, l1), lb = __halves2bfloat162(l2, l3);
        uint2 hv = make_uint2(*reinterpret_cast<uint32_t*>(&ha), *reinterpret_cast<uint32_t*>(&hb));
        uint2 lv = make_uint2(*reinterpret_cast<uint32_t*>(&la), *reinterpret_cast<uint32_t*>(&lb));
        reinterpret_cast<uint2*>(g_xh)[i] = hv;
        reinterpret_cast<uint2*>(g_xl)[i] = lv;
    }
}

// ---------------- pre-pass: convert + transpose weights ----------------
template<int W>
__global__ __launch_bounds__(256) void conv_transpose(const float* __restrict__ in) {
    constexpr int R = (W == 1) ? NEMBD : DFF;
    constexpr int C = (W == 1) ? DFF : NEMBD;
    __nv_bfloat16* oh = (W == 1) ? g_w1h : g_w2h;
    __nv_bfloat16* ol = (W == 1) ? g_w1l : g_w2l;
    __shared__ float t[32][33];
    const int e = blockIdx.z;
    const float* src = in + (size_t)e * R * C;
    __nv_bfloat16* dh = oh + (size_t)e * R * C;
    __nv_bfloat16* dl = ol + (size_t)e * R * C;
    const int c0 = blockIdx.x * 32, r0 = blockIdx.y * 32;
    const int tx = threadIdx.x & 31, ty = threadIdx.x >> 5;   // 32 x 8
    #pragma unroll
    for (int j = 0; j < 4; ++j)
        t[ty + j * 8][tx] = src[(size_t)(r0 + ty + j * 8) * C + c0 + tx];
    __syncthreads();
    #pragma unroll
    for (int j = 0; j < 4; ++j) {
        float v = t[tx][ty + j * 8];                     // in[r0+tx][c0+ty+j*8]
        __nv_bfloat16 hi, lo; split_bf16(v, hi, lo);
        size_t o = (size_t)(c0 + ty + j * 8) * R + r0 + tx;
        dh[o] = hi; dl[o] = lo;
    }
}

// ---------------- mma.sync grouped GEMM with bf16 hi/lo split ----------------
// CTA tile 256(m) x 128(n), BK=32, 512 threads = 16 warps as 4(m) x 4(n),
// warp tile 64x32. a*b ~= ah*bh + ah*bl + al*bh (residual ~2^-18).
template<bool DO_GELU>
__global__ __launch_bounds__(512, 1) void gemm_mma(const float* __restrict__ bias_all,
                                                   float* __restrict__ Cf) {
    constexpr int M = TOKENS;
    constexpr int N = DO_GELU ? DFF : NEMBD;
    constexpr int K = DO_GELU ? NEMBD : DFF;
    constexpr int NC = K / 32;             // k-chunks of 32
    constexpr int ROWB = 80;               // bytes per smem row (32 bf16 + 8 pad)
    constexpr int A_TILE = 256 * ROWB;     // 20480
    constexpr int B_TILE = 128 * ROWB;     // 10240
    constexpr int STAGE = 2 * A_TILE + 2 * B_TILE;   // 61440 (Ah, Al, Bh, Bl)

    const __nv_bfloat16* Ah = DO_GELU ? g_xh : g_hh;
    const __nv_bfloat16* Al = DO_GELU ? g_xl : g_hl;
    const __nv_bfloat16* Bh = DO_GELU ? g_w1h : g_w2h;
    const __nv_bfloat16* Bl = DO_GELU ? g_w1l : g_w2l;

    extern __shared__ __align__(1024) char smem[];
    const uint32_t sbase = smem_to_u32(smem);

    const int tid = threadIdx.x;
    const int wid = tid >> 5, lane = tid & 31;
    const int e = blockIdx.z;
    const int m0 = blockIdx.y * 256, n0 = blockIdx.x * 128;

    Ah += (size_t)e * M * K; Al += (size_t)e * M * K;
    Bh += (size_t)e * N * K; Bl += (size_t)e * N * K;
    const float* bias = bias_all + (size_t)e * N;

    // warp tile: 64(m) x 32(n); warps arranged 4(m) x 4(n)
    const int wm = (wid >> 2) * 64;
    const int wn = (wid & 3) * 32;

    float acc[4][4][4];
    #pragma unroll
    for (int i = 0; i < 4; ++i)
        #pragma unroll
        for (int j = 0; j < 4; ++j)
            #pragma unroll
            for (int q = 0; q < 4; ++q) acc[i][j][q] = 0.0f;

    // loader: chunk c -> stage s. 6 cp.async of 16B per thread (512 threads).
    auto load_stage = [&](int c, int s) {
        const int kt = c * 32;
        const uint32_t sb = sbase + s * STAGE;
        #pragma unroll
        for (int it = 0; it < 2; ++it) {          // A: 256 rows x 4 chunks = 1024 cp
            const int li  = tid + it * 512;
            const int row = li >> 2;
            const int ch  = li & 3;
            const uint32_t so = row * ROWB + ch * 16;
            const size_t  go = (size_t)(m0 + row) * K + kt + ch * 8;
            cp_async16(sb          + so, Ah + go);
            cp_async16(sb + A_TILE + so, Al + go);
        }
        {                                          // B: 128 rows x 4 chunks = 512 cp
            const int row = tid >> 2;
            const int ch  = tid & 3;
            const uint32_t so = row * ROWB + ch * 16;
            const size_t  go = (size_t)(n0 + row) * K + kt + ch * 8;
            cp_async16(sb + 2 * A_TILE          + so, Bh + go);
            cp_async16(sb + 2 * A_TILE + B_TILE + so, Bl + go);
        }
        CP_COMMIT();
    };

    load_stage(0, 0);
    load_stage(1, 1);

    // per-lane ldmatrix address components
    const uint32_t a_off = (uint32_t)((wm + (lane & 15)) * ROWB + (lane >> 4) * 16);
    const uint32_t b_off = (uint32_t)((wn + (lane & 7) + ((lane >> 4) << 3)) * ROWB + ((lane >> 3) & 1) * 16);

    for (int c = 0; c < NC; ++c) {
        if (c + 1 < NC) { CP_WAIT(1); } else { CP_WAIT(0); }
        __syncthreads();
        if (c + 2 < NC) load_stage(c + 2, (c + 2) % 3);

        const uint32_t sb = sbase + (c % 3) * STAGE;
        #pragma unroll
        for (int ks = 0; ks < 2; ++ks) {
            const uint32_t kso = (uint32_t)(ks * 32);
            uint32_t bfh[2][4], bfl[2][4];
            #pragma unroll
            for (int nt2 = 0; nt2 < 2; ++nt2) {
                const uint32_t bo = sb + 2 * A_TILE + b_off + kso + (uint32_t)(nt2 * 16 * ROWB);
                ldsm_x4(bfh[nt2], bo);
                ldsm_x4(bfl[nt2], bo + B_TILE);
            }
            #pragma unroll
            for (int mt = 0; mt < 4; ++mt) {
                uint32_t afh[4], afl[4];
                const uint32_t ao = sb + a_off + kso + (uint32_t)(mt * 16 * ROWB);
                ldsm_x4(afh, ao);
                ldsm_x4(afl, ao + A_TILE);
                #pragma unroll
                for (int nt = 0; nt < 4; ++nt)
                    mma_bf16(acc[mt][nt], afh, &bfh[nt >> 1][(nt & 1) * 2]);
                #pragma unroll
                for (int nt = 0; nt < 4; ++nt)
                    mma_bf16(acc[mt][nt], afh, &bfl[nt >> 1][(nt & 1) * 2]);
                #pragma unroll
                for (int nt = 0; nt < 4; ++nt)
                    mma_bf16(acc[mt][nt], afl, &bfh[nt >> 1][(nt & 1) * 2]);
            }
        }
    }

    // ---------------- epilogue ----------------
    const int groupID = lane >> 2, tig = lane & 3;
    #pragma unroll
    for (int mt = 0; mt < 4; ++mt) {
        const int r0g = m0 + wm + mt * 16 + groupID;
        #pragma unroll
        for (int nt = 0; nt < 4; ++nt) {
            const int col = n0 + wn + nt * 8 + tig * 2;
            const float2 bv = *reinterpret_cast<const float2*>(&bias[col]);
            float v0 = acc[mt][nt][0] + bv.x;
            float v1 = acc[mt][nt][1] + bv.y;
            float v2 = acc[mt][nt][2] + bv.x;
            float v3 = acc[mt][nt][3] + bv.y;
            if (DO_GELU) {
                v0 = gelu_exact(v0); v1 = gelu_exact(v1);
                v2 = gelu_exact(v2); v3 = gelu_exact(v3);
                __nv_bfloat16 h0, l0, h1, l1, h2, l2, h3, l3;
                split_bf16(v0, h0, l0); split_bf16(v1, h1, l1);
                split_bf16(v2, h2, l2); split_bf16(v3, h3, l3);
                const size_t o0 = ((size_t)e * M + r0g) * N + col;
                const size_t o1 = ((size_t)e * M + r0g + 8) * N + col;
                *reinterpret_cast<__nv_bfloat162*>(g_hh + o0) = __halves2bfloat162(h0, h1);
                *reinterpret_cast<__nv_bfloat162*>(g_hl + o0) = __halves2bfloat162(l0, l1);
                *reinterpret_cast<__nv_bfloat162*>(g_hh + o1) = __halves2bfloat162(h2, h3);
                *reinterpret_cast<__nv_bfloat162*>(g_hl + o1) = __halves2bfloat162(l2, l3);
            } else {
                const size_t o0 = ((size_t)e * M + r0g) * N + col;
                const size_t o1 = ((size_t)e * M + r0g + 8) * N + col;
                *reinterpret_cast<float2*>(Cf + o0) = make_float2(v0, v1);
                *reinterpret_cast<float2*>(Cf + o1) = make_float2(v2, v3);
            }
        }
    }
}

// ---------------- launch ----------------
extern "C" void kernel_launch(void* const* d_in, const int* in_sizes, int n_in,
                              void* d_out, int out_size) {
    const float* x         = (const float*)d_in[0];
    const float* c_fc      = (const float*)d_in[1];
    const float* c_proj    = (const float*)d_in[2];
    const float* fc_bias   = (const float*)d_in[3];
    const float* proj_bias = (const float*)d_in[4];
    float* out = (float*)d_out;

    constexpr int SMEM_BYTES = 3 * 61440;   // 184320
    cudaFuncSetAttribute(gemm_mma<true>,  cudaFuncAttributeMaxDynamicSharedMemorySize, SMEM_BYTES);
    cudaFuncSetAttribute(gemm_mma<false>, cudaFuncAttributeMaxDynamicSharedMemorySize, SMEM_BYTES);

    // pre-passes
    conv_split_x<<<4096, 256>>>(x);
    conv_transpose<1><<<dim3(DFF / 32, NEMBD / 32, NEXP), 256>>>(c_fc);
    conv_transpose<2><<<dim3(NEMBD / 32, DFF / 32, NEXP), 256>>>(c_proj);

    // GEMM1: [2048,1024] @ [1024,4096] + b1, gelu -> h (bf16 hi/lo)
    gemm_mma<true><<<dim3(DFF / 128, TOKENS / 256, NEXP), 512, SMEM_BYTES>>>(fc_bias, nullptr);
    // GEMM2: [2048,4096] @ [4096,1024] + b2 -> out (fp32)
    gemm_mma<false><<<dim3(NEMBD / 128, TOKENS / 256, NEXP), 512, SMEM_BYTES>>>(proj_bias, out);
}

// round 7
// speedup vs baseline: 3.0051x; 1.2759x over previous
#include <cuda_runtime.h>
#include <cuda_fp16.h>
#include <math.h>
#include <stdint.h>

#define NEXP   8
#define TOKENS 2048
#define NEMBD  1024
#define DFF    4096

// ---------------- device scratch (no runtime allocation) ----------------
__device__ __half g_xh[(size_t)NEXP * TOKENS * NEMBD];
__device__ __half g_xl[(size_t)NEXP * TOKENS * NEMBD];
__device__ __half g_w1h[(size_t)NEXP * DFF * NEMBD];   // [e][N=DFF][K=NEMBD], hi only
__device__ __half g_w2h[(size_t)NEXP * NEMBD * DFF];   // [e][N=NEMBD][K=DFF], hi only
__device__ __half g_hh[(size_t)NEXP * TOKENS * DFF];   // hidden hi
__device__ __half g_hl[(size_t)NEXP * TOKENS * DFF];   // hidden lo

// ---------------- helpers ----------------
__device__ __forceinline__ uint32_t smem_to_u32(const void* p) {
    uint32_t a;
    asm("{ .reg .u64 t; cvta.to.shared.u64 t, %1; cvt.u32.u64 %0, t; }" : "=r"(a) : "l"(p));
    return a;
}
__device__ __forceinline__ void cp_async16(uint32_t saddr, const void* gaddr) {
    asm volatile("cp.async.cg.shared.global [%0], [%1], 16;" :: "r"(saddr), "l"(gaddr));
}
#define CP_COMMIT() asm volatile("cp.async.commit_group;" ::: "memory")
#define CP_WAIT(n)  asm volatile("cp.async.wait_group %0;" :: "n"(n) : "memory")

__device__ __forceinline__ void ldsm_x4(uint32_t* r, uint32_t addr) {
    asm volatile("ldmatrix.sync.aligned.m8n8.x4.shared.b16 {%0,%1,%2,%3}, [%4];"
        : "=r"(r[0]), "=r"(r[1]), "=r"(r[2]), "=r"(r[3]) : "r"(addr));
}
__device__ __forceinline__ void mma_fp16(float* d, const uint32_t* a, const uint32_t* b) {
    asm volatile(
        "mma.sync.aligned.m16n8k16.row.col.f32.f16.f16.f32 "
        "{%0,%1,%2,%3}, {%4,%5,%6,%7}, {%8,%9}, {%0,%1,%2,%3};"
        : "+f"(d[0]), "+f"(d[1]), "+f"(d[2]), "+f"(d[3])
        : "r"(a[0]), "r"(a[1]), "r"(a[2]), "r"(a[3]), "r"(b[0]), "r"(b[1]));
}

__device__ __forceinline__ float gelu_exact(float x) {
    return 0.5f * x * (1.0f + erff(x * 0.70710678118654752440f));
}
__device__ __forceinline__ void split_fp16(float v, __half& hi, __half& lo) {
    hi = __float2half_rn(v);
    lo = __float2half_rn(v - __half2float(hi));
}

// ---------------- pre-pass: convert x -> fp16 hi/lo ----------------
__global__ __launch_bounds__(256) void conv_split_x(const float* __restrict__ x) {
    const size_t n4 = (size_t)NEXP * TOKENS * NEMBD / 4;
    const float4* in = reinterpret_cast<const float4*>(x);
    for (size_t i = blockIdx.x * 256ull + threadIdx.x; i < n4; i += (size_t)gridDim.x * 256) {
        float4 v = in[i];
        __half h0, h1, h2, h3, l0, l1, l2, l3;
        split_fp16(v.x, h0, l0); split_fp16(v.y, h1, l1);
        split_fp16(v.z, h2, l2); split_fp16(v.w, h3, l3);
        __half2 ha = __halves2half2(h0, h1), hb = __halves2half2(h2, h3);
        __half2 la = __halves2half2(l0, l1), lb = __halves2half2(l2, l3);
        uint2 hv = make_uint2(*reinterpret_cast<uint32_t*>(&ha), *reinterpret_cast<uint32_t*>(&hb));
        uint2 lv = make_uint2(*reinterpret_cast<uint32_t*>(&la), *reinterpret_cast<uint32_t*>(&lb));
        reinterpret_cast<uint2*>(g_xh)[i] = hv;
        reinterpret_cast<uint2*>(g_xl)[i] = lv;
    }
}

// ---------------- pre-pass: convert + transpose weights (hi only) ----------------
// W=1: c_fc [e][R=1024][C=4096] -> g_w1h [e][4096][1024]
// W=2: c_proj [e][R=4096][C=1024] -> g_w2h [e][1024][4096]
template<int W>
__global__ __launch_bounds__(256) void conv_transpose(const float* __restrict__ in) {
    constexpr int R = (W == 1) ? NEMBD : DFF;
    constexpr int C = (W == 1) ? DFF : NEMBD;
    __half* oh = (W == 1) ? g_w1h : g_w2h;
    __shared__ float t[32][33];
    const int e = blockIdx.z;
    const float* src = in + (size_t)e * R * C;
    __half* dh = oh + (size_t)e * R * C;
    const int c0 = blockIdx.x * 32, r0 = blockIdx.y * 32;
    const int tx = threadIdx.x & 31, ty = threadIdx.x >> 5;   // 32 x 8
    #pragma unroll
    for (int j = 0; j < 4; ++j)
        t[ty + j * 8][tx] = src[(size_t)(r0 + ty + j * 8) * C + c0 + tx];
    __syncthreads();
    #pragma unroll
    for (int j = 0; j < 4; ++j) {
        float v = t[tx][ty + j * 8];                     // in[r0+tx][c0+ty+j*8]
        size_t o = (size_t)(c0 + ty + j * 8) * R + r0 + tx;
        dh[o] = __float2half_rn(v);
    }
}

// ---------------- mma.sync grouped GEMM with fp16 2-term split ----------------
// CTA tile 256(m) x 128(n), BK=32, 512 threads = 16 warps as 4(m) x 4(n),
// warp tile 64x32. a*b ~= ah*bh + al*bh (weight-lo dropped, residual ~2^-11 of b).
template<bool DO_GELU>
__global__ __launch_bounds__(512, 1) void gemm_mma(const float* __restrict__ bias_all,
                                                   float* __restrict__ Cf) {
    constexpr int M = TOKENS;
    constexpr int N = DO_GELU ? DFF : NEMBD;
    constexpr int K = DO_GELU ? NEMBD : DFF;
    constexpr int NC = K / 32;             // k-chunks of 32
    constexpr int ROWB = 80;               // bytes per smem row (32 fp16 + 8 pad)
    constexpr int A_TILE = 256 * ROWB;     // 20480
    constexpr int B_TILE = 128 * ROWB;     // 10240
    constexpr int STAGE = 2 * A_TILE + B_TILE;   // 51200 (Ah, Al, Bh)
    constexpr int NSTAGE = 4;

    const __half* Ah = DO_GELU ? g_xh : g_hh;
    const __half* Al = DO_GELU ? g_xl : g_hl;
    const __half* Bh = DO_GELU ? g_w1h : g_w2h;

    extern __shared__ __align__(1024) char smem[];
    const uint32_t sbase = smem_to_u32(smem);

    const int tid = threadIdx.x;
    const int wid = tid >> 5, lane = tid & 31;
    const int e = blockIdx.z;
    const int m0 = blockIdx.y * 256, n0 = blockIdx.x * 128;

    Ah += (size_t)e * M * K; Al += (size_t)e * M * K;
    Bh += (size_t)e * N * K;
    const float* bias = bias_all + (size_t)e * N;

    // warp tile: 64(m) x 32(n); warps arranged 4(m) x 4(n)
    const int wm = (wid >> 2) * 64;
    const int wn = (wid & 3) * 32;

    float acc[4][4][4];
    #pragma unroll
    for (int i = 0; i < 4; ++i)
        #pragma unroll
        for (int j = 0; j < 4; ++j)
            #pragma unroll
            for (int q = 0; q < 4; ++q) acc[i][j][q] = 0.0f;

    // loader: chunk c -> stage s. 5 cp.async of 16B per thread (512 threads).
    auto load_stage = [&](int c, int s) {
        const int kt = c * 32;
        const uint32_t sb = sbase + s * STAGE;
        #pragma unroll
        for (int it = 0; it < 2; ++it) {          // A: 256 rows x 4 chunks = 1024 slots
            const int li  = tid + it * 512;
            const int row = li >> 2;
            const int ch  = li & 3;
            const uint32_t so = row * ROWB + ch * 16;
            const size_t  go = (size_t)(m0 + row) * K + kt + ch * 8;
            cp_async16(sb          + so, Ah + go);
            cp_async16(sb + A_TILE + so, Al + go);
        }
        {                                          // B: 128 rows x 4 chunks = 512 slots
            const int row = tid >> 2;
            const int ch  = tid & 3;
            const uint32_t so = row * ROWB + ch * 16;
            const size_t  go = (size_t)(n0 + row) * K + kt + ch * 8;
            cp_async16(sb + 2 * A_TILE + so, Bh + go);
        }
        CP_COMMIT();
    };

    load_stage(0, 0);
    load_stage(1, 1);
    load_stage(2, 2);

    // per-lane ldmatrix address components
    const uint32_t a_off = (uint32_t)((wm + (lane & 15)) * ROWB + (lane >> 4) * 16);
    const uint32_t b_off = (uint32_t)((wn + (lane & 7) + ((lane >> 4) << 3)) * ROWB + ((lane >> 3) & 1) * 16);

    for (int c = 0; c < NC; ++c) {
        if (c + 2 < NC)      { CP_WAIT(2); }
        else if (c + 1 < NC) { CP_WAIT(1); }
        else                 { CP_WAIT(0); }
        __syncthreads();
        if (c + 3 < NC) load_stage(c + 3, (c + 3) & (NSTAGE - 1));

        const uint32_t sb = sbase + (c & (NSTAGE - 1)) * STAGE;
        #pragma unroll
        for (int ks = 0; ks < 2; ++ks) {
            const uint32_t kso = (uint32_t)(ks * 32);
            uint32_t bfh[2][4];
            #pragma unroll
            for (int nt2 = 0; nt2 < 2; ++nt2) {
                const uint32_t bo = sb + 2 * A_TILE + b_off + kso + (uint32_t)(nt2 * 16 * ROWB);
                ldsm_x4(bfh[nt2], bo);
            }
            #pragma unroll
            for (int mt = 0; mt < 4; ++mt) {
                uint32_t afh[4], afl[4];
                const uint32_t ao = sb + a_off + kso + (uint32_t)(mt * 16 * ROWB);
                ldsm_x4(afh, ao);
                ldsm_x4(afl, ao + A_TILE);
                #pragma unroll
                for (int nt = 0; nt < 4; ++nt)
                    mma_fp16(acc[mt][nt], afh, &bfh[nt >> 1][(nt & 1) * 2]);
                #pragma unroll
                for (int nt = 0; nt < 4; ++nt)
                    mma_fp16(acc[mt][nt], afl, &bfh[nt >> 1][(nt & 1) * 2]);
            }
        }
    }

    // ---------------- epilogue ----------------
    const int groupID = lane >> 2, tig = lane & 3;
    #pragma unroll
    for (int mt = 0; mt < 4; ++mt) {
        const int r0g = m0 + wm + mt * 16 + groupID;
        #pragma unroll
        for (int nt = 0; nt < 4; ++nt) {
            const int col = n0 + wn + nt * 8 + tig * 2;
            const float2 bv = *reinterpret_cast<const float2*>(&bias[col]);
            float v0 = acc[mt][nt][0] + bv.x;
            float v1 = acc[mt][nt][1] + bv.y;
            float v2 = acc[mt][nt][2] + bv.x;
            float v3 = acc[mt][nt][3] + bv.y;
            if (DO_GELU) {
                v0 = gelu_exact(v0); v1 = gelu_exact(v1);
                v2 = gelu_exact(v2); v3 = gelu_exact(v3);
                __half h0, l0, h1, l1, h2, l2, h3, l3;
                split_fp16(v0, h0, l0); split_fp16(v1, h1, l1);
                split_fp16(v2, h2, l2); split_fp16(v3, h3, l3);
                const size_t o0 = ((size_t)e * M + r0g) * N + col;
                const size_t o1 = ((size_t)e * M + r0g + 8) * N + col;
                *reinterpret_cast<__half2*>(g_hh + o0) = __halves2half2(h0, h1);
                *reinterpret_cast<__half2*>(g_hl + o0) = __halves2half2(l0, l1);
                *reinterpret_cast<__half2*>(g_hh + o1) = __halves2half2(h2, h3);
                *reinterpret_cast<__half2*>(g_hl + o1) = __halves2half2(l2, l3);
            } else {
                const size_t o0 = ((size_t)e * M + r0g) * N + col;
                const size_t o1 = ((size_t)e * M + r0g + 8) * N + col;
                *reinterpret_cast<float2*>(Cf + o0) = make_float2(v0, v1);
                *reinterpret_cast<float2*>(Cf + o1) = make_float2(v2, v3);
            }
        }
    }
}

// ---------------- launch ----------------
extern "C" void kernel_launch(void* const* d_in, const int* in_sizes, int n_in,
                              void* d_out, int out_size) {
    const float* x         = (const float*)d_in[0];
    const float* c_fc      = (const float*)d_in[1];
    const float* c_proj    = (const float*)d_in[2];
    const float* fc_bias   = (const float*)d_in[3];
    const float* proj_bias = (const float*)d_in[4];
    float* out = (float*)d_out;

    constexpr int SMEM_BYTES = 4 * 51200;   // 204800
    cudaFuncSetAttribute(gemm_mma<true>,  cudaFuncAttributeMaxDynamicSharedMemorySize, SMEM_BYTES);
    cudaFuncSetAttribute(gemm_mma<false>, cudaFuncAttributeMaxDynamicSharedMemorySize, SMEM_BYTES);

    // pre-passes
    conv_split_x<<<4096, 256>>>(x);
    conv_transpose<1><<<dim3(DFF / 32, NEMBD / 32, NEXP), 256>>>(c_fc);
    conv_transpose<2><<<dim3(NEMBD / 32, DFF / 32, NEXP), 256>>>(c_proj);

    // GEMM1: [2048,1024] @ [1024,4096] + b1, gelu -> h (fp16 hi/lo)
    gemm_mma<true><<<dim3(DFF / 128, TOKENS / 256, NEXP), 512, SMEM_BYTES>>>(fc_bias, nullptr);
    // GEMM2: [2048,4096] @ [4096,1024] + b2 -> out (fp32)
    gemm_mma<false><<<dim3(NEMBD / 128, TOKENS / 256, NEXP), 512, SMEM_BYTES>>>(proj_bias, out);
}

// round 8
// speedup vs baseline: 4.9142x; 1.6353x over previous
#include <cuda_runtime.h>
#include <cuda_fp16.h>
#include <math.h>
#include <stdint.h>

#define NEXP   8
#define TOKENS 2048
#define NEMBD  1024
#define DFF    4096

// ---------------- device scratch (no runtime allocation) ----------------
__device__ __half g_x16[(size_t)NEXP * TOKENS * NEMBD];
__device__ __half g_w1[(size_t)NEXP * DFF * NEMBD];   // [e][N=DFF][K=NEMBD]
__device__ __half g_w2[(size_t)NEXP * NEMBD * DFF];   // [e][N=NEMBD][K=DFF]
__device__ __half g_h16[(size_t)NEXP * TOKENS * DFF]; // hidden (post-GELU)

// ---------------- helpers ----------------
__device__ __forceinline__ uint32_t smem_to_u32(const void* p) {
    uint32_t a;
    asm("{ .reg .u64 t; cvta.to.shared.u64 t, %1; cvt.u32.u64 %0, t; }" : "=r"(a) : "l"(p));
    return a;
}
__device__ __forceinline__ void cp_async16(uint32_t saddr, const void* gaddr) {
    asm volatile("cp.async.cg.shared.global [%0], [%1], 16;" :: "r"(saddr), "l"(gaddr));
}
#define CP_COMMIT() asm volatile("cp.async.commit_group;" ::: "memory")
#define CP_WAIT(n)  asm volatile("cp.async.wait_group %0;" :: "n"(n) : "memory")

__device__ __forceinline__ void ldsm_x4(uint32_t* r, uint32_t addr) {
    asm volatile("ldmatrix.sync.aligned.m8n8.x4.shared.b16 {%0,%1,%2,%3}, [%4];"
        : "=r"(r[0]), "=r"(r[1]), "=r"(r[2]), "=r"(r[3]) : "r"(addr));
}
__device__ __forceinline__ void mma_fp16(float* d, const uint32_t* a, const uint32_t* b) {
    asm volatile(
        "mma.sync.aligned.m16n8k16.row.col.f32.f16.f16.f32 "
        "{%0,%1,%2,%3}, {%4,%5,%6,%7}, {%8,%9}, {%0,%1,%2,%3};"
        : "+f"(d[0]), "+f"(d[1]), "+f"(d[2]), "+f"(d[3])
        : "r"(a[0]), "r"(a[1]), "r"(a[2]), "r"(a[3]), "r"(b[0]), "r"(b[1]));
}

__device__ __forceinline__ float gelu_exact(float x) {
    return 0.5f * x * (1.0f + erff(x * 0.70710678118654752440f));
}

// ---------------- pre-pass: convert x -> fp16 ----------------
__global__ __launch_bounds__(256) void conv_x(const float* __restrict__ x) {
    const size_t n4 = (size_t)NEXP * TOKENS * NEMBD / 4;
    const float4* in = reinterpret_cast<const float4*>(x);
    for (size_t i = blockIdx.x * 256ull + threadIdx.x; i < n4; i += (size_t)gridDim.x * 256) {
        float4 v = in[i];
        __half2 a = __halves2half2(__float2half_rn(v.x), __float2half_rn(v.y));
        __half2 b = __halves2half2(__float2half_rn(v.z), __float2half_rn(v.w));
        reinterpret_cast<uint2*>(g_x16)[i] =
            make_uint2(*reinterpret_cast<uint32_t*>(&a), *reinterpret_cast<uint32_t*>(&b));
    }
}

// ---------------- pre-pass: convert + transpose weights ----------------
// W=1: c_fc [e][R=1024][C=4096] -> g_w1 [e][4096][1024]
// W=2: c_proj [e][R=4096][C=1024] -> g_w2 [e][1024][4096]
template<int W>
__global__ __launch_bounds__(256) void conv_transpose(const float* __restrict__ in) {
    constexpr int R = (W == 1) ? NEMBD : DFF;
    constexpr int C = (W == 1) ? DFF : NEMBD;
    __half* oh = (W == 1) ? g_w1 : g_w2;
    __shared__ float t[32][33];
    const int e = blockIdx.z;
    const float* src = in + (size_t)e * R * C;
    __half* dh = oh + (size_t)e * R * C;
    const int c0 = blockIdx.x * 32, r0 = blockIdx.y * 32;
    const int tx = threadIdx.x & 31, ty = threadIdx.x >> 5;   // 32 x 8
    #pragma unroll
    for (int j = 0; j < 4; ++j)
        t[ty + j * 8][tx] = src[(size_t)(r0 + ty + j * 8) * C + c0 + tx];
    __syncthreads();
    #pragma unroll
    for (int j = 0; j < 4; ++j) {
        float v = t[tx][ty + j * 8];                     // in[r0+tx][c0+ty+j*8]
        size_t o = (size_t)(c0 + ty + j * 8) * R + r0 + tx;
        dh[o] = __float2half_rn(v);
    }
}

// ---------------- mma.sync grouped GEMM, plain fp16 ----------------
// CTA tile 256(m) x 128(n), BK=32, 512 threads = 16 warps as 4(m) x 4(n),
// warp tile 64x32. 6-stage cp.async pipeline.
template<bool DO_GELU>
__global__ __launch_bounds__(512, 1) void gemm_mma(const float* __restrict__ bias_all,
                                                   float* __restrict__ Cf) {
    constexpr int M = TOKENS;
    constexpr int N = DO_GELU ? DFF : NEMBD;
    constexpr int K = DO_GELU ? NEMBD : DFF;
    constexpr int NC = K / 32;             // k-chunks of 32
    constexpr int ROWB = 80;               // bytes per smem row (32 fp16 + 8 pad)
    constexpr int A_TILE = 256 * ROWB;     // 20480
    constexpr int B_TILE = 128 * ROWB;     // 10240
    constexpr int STAGE = A_TILE + B_TILE; // 30720
    constexpr int NSTAGE = 6;

    const __half* A = DO_GELU ? g_x16 : g_h16;
    const __half* B = DO_GELU ? g_w1 : g_w2;

    extern __shared__ __align__(1024) char smem[];
    const uint32_t sbase = smem_to_u32(smem);

    const int tid = threadIdx.x;
    const int wid = tid >> 5, lane = tid & 31;
    const int e = blockIdx.z;
    const int m0 = blockIdx.y * 256, n0 = blockIdx.x * 128;

    A += (size_t)e * M * K;
    B += (size_t)e * N * K;
    const float* bias = bias_all + (size_t)e * N;

    // warp tile: 64(m) x 32(n); warps arranged 4(m) x 4(n)
    const int wm = (wid >> 2) * 64;
    const int wn = (wid & 3) * 32;

    float acc[4][4][4];
    #pragma unroll
    for (int i = 0; i < 4; ++i)
        #pragma unroll
        for (int j = 0; j < 4; ++j)
            #pragma unroll
            for (int q = 0; q < 4; ++q) acc[i][j][q] = 0.0f;

    // loader: chunk c -> stage s. 3 cp.async of 16B per thread (512 threads).
    auto load_stage = [&](int c, int s) {
        const int kt = c * 32;
        const uint32_t sb = sbase + s * STAGE;
        #pragma unroll
        for (int it = 0; it < 2; ++it) {          // A: 256 rows x 4 chunks = 1024 slots
            const int li  = tid + it * 512;
            const int row = li >> 2;
            const int ch  = li & 3;
            const uint32_t so = row * ROWB + ch * 16;
            cp_async16(sb + so, A + (size_t)(m0 + row) * K + kt + ch * 8);
        }
        {                                          // B: 128 rows x 4 chunks = 512 slots
            const int row = tid >> 2;
            const int ch  = tid & 3;
            const uint32_t so = row * ROWB + ch * 16;
            cp_async16(sb + A_TILE + so, B + (size_t)(n0 + row) * K + kt + ch * 8);
        }
        CP_COMMIT();
    };

    #pragma unroll
    for (int p = 0; p < 5; ++p) load_stage(p, p);   // NC >= 32 always

    // per-lane ldmatrix address components
    const uint32_t a_off = (uint32_t)((wm + (lane & 15)) * ROWB + (lane >> 4) * 16);
    const uint32_t b_off = (uint32_t)((wn + (lane & 7) + ((lane >> 4) << 3)) * ROWB + ((lane >> 3) & 1) * 16);

    int s = 0;
    for (int c = 0; c < NC; ++c) {
        const int inflight = (NC - c > 5) ? 5 : (NC - c);
        if (inflight > 4)      { CP_WAIT(4); }
        else if (inflight > 3) { CP_WAIT(3); }
        else if (inflight > 2) { CP_WAIT(2); }
        else if (inflight > 1) { CP_WAIT(1); }
        else                   { CP_WAIT(0); }
        __syncthreads();
        if (c + 5 < NC) {
            int s5 = s + 5; if (s5 >= NSTAGE) s5 -= NSTAGE;
            load_stage(c + 5, s5);
        }

        const uint32_t sb = sbase + s * STAGE;
        if (++s == NSTAGE) s = 0;
        #pragma unroll
        for (int ks = 0; ks < 2; ++ks) {
            const uint32_t kso = (uint32_t)(ks * 32);
            uint32_t bf[2][4];
            #pragma unroll
            for (int nt2 = 0; nt2 < 2; ++nt2)
                ldsm_x4(bf[nt2], sb + A_TILE + b_off + kso + (uint32_t)(nt2 * 16 * ROWB));
            #pragma unroll
            for (int mt = 0; mt < 4; ++mt) {
                uint32_t af[4];
                ldsm_x4(af, sb + a_off + kso + (uint32_t)(mt * 16 * ROWB));
                #pragma unroll
                for (int nt = 0; nt < 4; ++nt)
                    mma_fp16(acc[mt][nt], af, &bf[nt >> 1][(nt & 1) * 2]);
            }
        }
    }

    // ---------------- epilogue ----------------
    const int groupID = lane >> 2, tig = lane & 3;
    #pragma unroll
    for (int mt = 0; mt < 4; ++mt) {
        const int r0g = m0 + wm + mt * 16 + groupID;
        #pragma unroll
        for (int nt = 0; nt < 4; ++nt) {
            const int col = n0 + wn + nt * 8 + tig * 2;
            const float2 bv = *reinterpret_cast<const float2*>(&bias[col]);
            float v0 = acc[mt][nt][0] + bv.x;
            float v1 = acc[mt][nt][1] + bv.y;
            float v2 = acc[mt][nt][2] + bv.x;
            float v3 = acc[mt][nt][3] + bv.y;
            if (DO_GELU) {
                v0 = gelu_exact(v0); v1 = gelu_exact(v1);
                v2 = gelu_exact(v2); v3 = gelu_exact(v3);
                const size_t o0 = ((size_t)e * M + r0g) * N + col;
                const size_t o1 = ((size_t)e * M + r0g + 8) * N + col;
                *reinterpret_cast<__half2*>(g_h16 + o0) =
                    __halves2half2(__float2half_rn(v0), __float2half_rn(v1));
                *reinterpret_cast<__half2*>(g_h16 + o1) =
                    __halves2half2(__float2half_rn(v2), __float2half_rn(v3));
            } else {
                const size_t o0 = ((size_t)e * M + r0g) * N + col;
                const size_t o1 = ((size_t)e * M + r0g + 8) * N + col;
                *reinterpret_cast<float2*>(Cf + o0) = make_float2(v0, v1);
                *reinterpret_cast<float2*>(Cf + o1) = make_float2(v2, v3);
            }
        }
    }
}

// ---------------- launch ----------------
extern "C" void kernel_launch(void* const* d_in, const int* in_sizes, int n_in,
                              void* d_out, int out_size) {
    const float* x         = (const float*)d_in[0];
    const float* c_fc      = (const float*)d_in[1];
    const float* c_proj    = (const float*)d_in[2];
    const float* fc_bias   = (const float*)d_in[3];
    const float* proj_bias = (const float*)d_in[4];
    float* out = (float*)d_out;

    constexpr int SMEM_BYTES = 6 * 30720;   // 184320
    cudaFuncSetAttribute(gemm_mma<true>,  cudaFuncAttributeMaxDynamicSharedMemorySize, SMEM_BYTES);
    cudaFuncSetAttribute(gemm_mma<false>, cudaFuncAttributeMaxDynamicSharedMemorySize, SMEM_BYTES);

    // pre-passes
    conv_x<<<4096, 256>>>(x);
    conv_transpose<1><<<dim3(DFF / 32, NEMBD / 32, NEXP), 256>>>(c_fc);
    conv_transpose<2><<<dim3(NEMBD / 32, DFF / 32, NEXP), 256>>>(c_proj);

    // GEMM1: [2048,1024] @ [1024,4096] + b1, gelu -> h (fp16)
    gemm_mma<true><<<dim3(DFF / 128, TOKENS / 256, NEXP), 512, SMEM_BYTES>>>(fc_bias, nullptr);
    // GEMM2: [2048,4096] @ [4096,1024] + b2 -> out (fp32)
    gemm_mma<false><<<dim3(NEMBD / 128, TOKENS / 256, NEXP), 512, SMEM_BYTES>>>(proj_bias, out);
}